// round 1
// baseline (speedup 1.0000x reference)
#include <cuda_runtime.h>

#define NV 256
#define DIM 1024
#define DIM4 256          // 1024 floats / 4
#define TM 64             // GEMM tile (M and N)
#define KC 64             // K-chunk per block
#define KSPLIT 16         // 1024 / KC

// Scratch (no allocations allowed)
__device__ float gA[NV * DIM];     // group sums of im
__device__ float gB[NV * DIM];     // group sums of s
__device__ float gS[NV * NV];      // block sums A @ B^T

// ---------------------------------------------------------------------------
// Kernel 1: segment-sum both im and s into gA / gB. Also zeros gS.
// grid = 512 blocks (256 im-groups, 256 s-groups), 256 threads each.
// Each thread owns one float4 column (4 of 1024 dims), loops over group rows.
// ---------------------------------------------------------------------------
__global__ __launch_bounds__(256) void seg_reduce_kernel(
    const float* __restrict__ im, const float* __restrict__ sc,
    const int* __restrict__ ncl, const int* __restrict__ ncp)
{
    int b = blockIdx.x;
    int t = threadIdx.x;

    // fold gS zeroing into this kernel: 512 blocks * 128 threads = 65536
    if (t < 128) gS[b * 128 + t] = 0.0f;

    int g = b & 255;
    const int*    cnts = (b < 256) ? ncl : ncp;
    const float4* src  = (b < 256) ? (const float4*)im : (const float4*)sc;
    float4*       dst  = (b < 256) ? (float4*)gA : (float4*)gB;

    // offset = sum of counts[0..g) via block reduction
    int v = (t < g) ? cnts[t] : 0;
    #pragma unroll
    for (int o = 16; o > 0; o >>= 1) v += __shfl_down_sync(0xffffffffu, v, o);
    __shared__ int wsum[8];
    if ((t & 31) == 0) wsum[t >> 5] = v;
    __syncthreads();
    int off = 0;
    #pragma unroll
    for (int w = 0; w < 8; w++) off += wsum[w];

    int cnt = cnts[g];
    const float4* p = src + (size_t)off * DIM4 + t;
    float ax = 0.f, ay = 0.f, az = 0.f, aw = 0.f;
    int r = 0;
    for (; r + 4 <= cnt; r += 4) {
        float4 a0 = p[(size_t)(r + 0) * DIM4];
        float4 a1 = p[(size_t)(r + 1) * DIM4];
        float4 a2 = p[(size_t)(r + 2) * DIM4];
        float4 a3 = p[(size_t)(r + 3) * DIM4];
        ax += (a0.x + a1.x) + (a2.x + a3.x);
        ay += (a0.y + a1.y) + (a2.y + a3.y);
        az += (a0.z + a1.z) + (a2.z + a3.z);
        aw += (a0.w + a1.w) + (a2.w + a3.w);
    }
    for (; r < cnt; r++) {
        float4 a = p[(size_t)r * DIM4];
        ax += a.x; ay += a.y; az += a.z; aw += a.w;
    }
    dst[g * DIM4 + t] = make_float4(ax, ay, az, aw);
}

// ---------------------------------------------------------------------------
// Kernel 2: split-K GEMM  gS += A[64-tile] @ B[64-tile]^T over a 64-wide K slice.
// grid = (4, 4, 16), block = (16, 16). 4x4 register tile per thread.
// Shared tiles stored k-major [KC][68]; pad 68 keeps float4 alignment for
// compute loads while breaking the worst store bank conflicts.
// ---------------------------------------------------------------------------
__global__ __launch_bounds__(256) void gemm_kernel()
{
    __shared__ float As[KC][68];
    __shared__ float Bs[KC][68];

    int tx = threadIdx.x, ty = threadIdx.y;
    int tid = ty * 16 + tx;
    int m0  = blockIdx.x * TM;
    int n0  = blockIdx.y * TM;
    int kq0 = blockIdx.z * (KC / 4);   // float4 index into K

    const float4* Ag = (const float4*)gA;
    const float4* Bg = (const float4*)gB;

    // 64 rows x 16 float4 = 1024 float4 per operand; 4 per thread
    #pragma unroll
    for (int i = 0; i < 4; i++) {
        int li = tid + i * 256;
        int m  = li >> 4;          // row within tile
        int kq = li & 15;          // float4 within K-chunk
        int k  = kq * 4;
        float4 a  = Ag[(size_t)(m0 + m) * DIM4 + kq0 + kq];
        As[k][m] = a.x; As[k + 1][m] = a.y; As[k + 2][m] = a.z; As[k + 3][m] = a.w;
        float4 bv = Bg[(size_t)(n0 + m) * DIM4 + kq0 + kq];
        Bs[k][m] = bv.x; Bs[k + 1][m] = bv.y; Bs[k + 2][m] = bv.z; Bs[k + 3][m] = bv.w;
    }
    __syncthreads();

    float acc[4][4] = {};
    #pragma unroll 16
    for (int k = 0; k < KC; k++) {
        float4 a  = *(const float4*)&As[k][ty * 4];
        float4 bv = *(const float4*)&Bs[k][tx * 4];
        acc[0][0] += a.x * bv.x; acc[0][1] += a.x * bv.y; acc[0][2] += a.x * bv.z; acc[0][3] += a.x * bv.w;
        acc[1][0] += a.y * bv.x; acc[1][1] += a.y * bv.y; acc[1][2] += a.y * bv.z; acc[1][3] += a.y * bv.w;
        acc[2][0] += a.z * bv.x; acc[2][1] += a.z * bv.y; acc[2][2] += a.z * bv.z; acc[2][3] += a.z * bv.w;
        acc[3][0] += a.w * bv.x; acc[3][1] += a.w * bv.y; acc[3][2] += a.w * bv.z; acc[3][3] += a.w * bv.w;
    }

    int m = m0 + ty * 4;
    int n = n0 + tx * 4;
    #pragma unroll
    for (int r = 0; r < 4; r++)
        #pragma unroll
        for (int c = 0; c < 4; c++)
            atomicAdd(&gS[(m + r) * NV + n + c], acc[r][c]);
}

// ---------------------------------------------------------------------------
// Kernel 3: hinge loss + reduction. Single block, 1024 threads, 64 elems each.
// ---------------------------------------------------------------------------
__global__ __launch_bounds__(1024) void loss_kernel(
    const int* __restrict__ ncl, const int* __restrict__ ncp,
    float* __restrict__ out)
{
    __shared__ float dg[256];   // diagonal of S
    __shared__ float rc[256];   // num_clips as float
    __shared__ float rp[256];   // num_caps as float

    int t = threadIdx.x;
    if (t < 256) {
        float nc = (float)ncl[t];
        float np = (float)ncp[t];
        rc[t] = nc; rp[t] = np;
        dg[t] = gS[t * 257] / (nc * np);
    }
    __syncthreads();

    float sum = 0.f;
    #pragma unroll
    for (int it = 0; it < 64; it++) {
        int idx = t + it * 1024;
        int i = idx >> 8;
        int j = idx & 255;
        float sv = gS[idx] / (rc[i] * rp[j]);
        if (i != j)
            sum += fmaxf(sv - dg[i], 0.f) + fmaxf(sv - dg[j], 0.f);
    }

    #pragma unroll
    for (int o = 16; o > 0; o >>= 1) sum += __shfl_down_sync(0xffffffffu, sum, o);
    __shared__ float ws[32];
    if ((t & 31) == 0) ws[t >> 5] = sum;
    __syncthreads();
    if (t < 32) {
        float v = ws[t];
        #pragma unroll
        for (int o = 16; o > 0; o >>= 1) v += __shfl_down_sync(0xffffffffu, v, o);
        if (t == 0) out[0] = v;
    }
}

extern "C" void kernel_launch(void* const* d_in, const int* in_sizes, int n_in,
                              void* d_out, int out_size)
{
    const float* im  = (const float*)d_in[0];
    const float* sc  = (const float*)d_in[1];
    const int*   ncl = (const int*)d_in[2];
    const int*   ncp = (const int*)d_in[3];

    seg_reduce_kernel<<<512, 256>>>(im, sc, ncl, ncp);
    gemm_kernel<<<dim3(4, 4, KSPLIT), dim3(16, 16)>>>();
    loss_kernel<<<1, 1024>>>(ncl, ncp, (float*)d_out);
}

// round 2
// speedup vs baseline: 1.1139x; 1.1139x over previous
#include <cuda_runtime.h>

#define NV 256
#define DIM 1024
#define DIM4 256          // 1024 floats / 4
#define TM 64             // GEMM tile (M and N)
#define KC 64             // K-chunk per smem fill
#define KSPLIT 8          // K split factor (each block does 2 KC chunks = 128)

// Scratch (no allocations allowed)
__device__ float gA[NV * DIM];            // group sums of im
__device__ float gB[NV * DIM];            // group sums of s
__device__ float gSp[KSPLIT * NV * NV];   // split-K partial block sums
__device__ float gS[NV * NV];             // reduced block sums A @ B^T

// ---------------------------------------------------------------------------
// Kernel 1: segment-sum im -> gA and s -> gB.
// grid = 1024 blocks: b -> (is_im, group, dim-half). 128 threads each,
// one float4 column per thread. Unroll-8 row batching for MLP.
// ---------------------------------------------------------------------------
__global__ __launch_bounds__(128) void seg_reduce_kernel(
    const float* __restrict__ im, const float* __restrict__ sc,
    const int* __restrict__ ncl, const int* __restrict__ ncp)
{
    int b = blockIdx.x;
    int t = threadIdx.x;

    int g2 = b >> 1;           // 0..511
    int h  = b & 1;            // dim half
    int g  = g2 & 255;         // group id
    const int*    cnts = (g2 < 256) ? ncl : ncp;
    const float4* src  = (g2 < 256) ? (const float4*)im : (const float4*)sc;
    float4*       dst  = (g2 < 256) ? (float4*)gA : (float4*)gB;

    // offset = sum of counts[0..g) via 128-thread block reduction
    int v = ((t < g) ? cnts[t] : 0) + ((t + 128 < g) ? cnts[t + 128] : 0);
    #pragma unroll
    for (int o = 16; o > 0; o >>= 1) v += __shfl_down_sync(0xffffffffu, v, o);
    __shared__ int wsum[4];
    if ((t & 31) == 0) wsum[t >> 5] = v;
    __syncthreads();
    int off = wsum[0] + wsum[1] + wsum[2] + wsum[3];

    int cnt = cnts[g];
    int col = h * 128 + t;                       // float4 column 0..255
    const float4* p = src + (size_t)off * DIM4 + col;
    float ax = 0.f, ay = 0.f, az = 0.f, aw = 0.f;
    int r = 0;
    for (; r + 8 <= cnt; r += 8) {
        float4 a0 = __ldcs(&p[(size_t)(r + 0) * DIM4]);
        float4 a1 = __ldcs(&p[(size_t)(r + 1) * DIM4]);
        float4 a2 = __ldcs(&p[(size_t)(r + 2) * DIM4]);
        float4 a3 = __ldcs(&p[(size_t)(r + 3) * DIM4]);
        float4 a4 = __ldcs(&p[(size_t)(r + 4) * DIM4]);
        float4 a5 = __ldcs(&p[(size_t)(r + 5) * DIM4]);
        float4 a6 = __ldcs(&p[(size_t)(r + 6) * DIM4]);
        float4 a7 = __ldcs(&p[(size_t)(r + 7) * DIM4]);
        ax += ((a0.x + a1.x) + (a2.x + a3.x)) + ((a4.x + a5.x) + (a6.x + a7.x));
        ay += ((a0.y + a1.y) + (a2.y + a3.y)) + ((a4.y + a5.y) + (a6.y + a7.y));
        az += ((a0.z + a1.z) + (a2.z + a3.z)) + ((a4.z + a5.z) + (a6.z + a7.z));
        aw += ((a0.w + a1.w) + (a2.w + a3.w)) + ((a4.w + a5.w) + (a6.w + a7.w));
    }
    for (; r < cnt; r++) {
        float4 a = __ldcs(&p[(size_t)r * DIM4]);
        ax += a.x; ay += a.y; az += a.z; aw += a.w;
    }
    dst[g * DIM4 + col] = make_float4(ax, ay, az, aw);
}

// ---------------------------------------------------------------------------
// Kernel 2: split-K GEMM. Each block computes a 64x64 output tile over a
// 128-wide K slice (two 64-wide smem fills) and stores its partial to gSp
// with plain STG.128 (no atomics, no collisions).
// grid = (4, 4, 8), block = (16, 16), 4x4 register tile per thread.
// ---------------------------------------------------------------------------
__global__ __launch_bounds__(256) void gemm_kernel()
{
    __shared__ float As[KC][68];
    __shared__ float Bs[KC][68];

    int tx = threadIdx.x, ty = threadIdx.y;
    int tid = ty * 16 + tx;
    int m0  = blockIdx.x * TM;
    int n0  = blockIdx.y * TM;
    int kz  = blockIdx.z;

    const float4* Ag = (const float4*)gA;
    const float4* Bg = (const float4*)gB;

    float acc[4][4] = {};

    #pragma unroll
    for (int kk = 0; kk < 2; kk++) {
        int kq0 = kz * 32 + kk * 16;   // float4 index into K
        if (kk) __syncthreads();
        // 64 rows x 16 float4 per operand; 4 per thread
        #pragma unroll
        for (int i = 0; i < 4; i++) {
            int li = tid + i * 256;
            int m  = li >> 4;          // row within tile
            int kq = li & 15;          // float4 within K-chunk
            int k  = kq * 4;
            float4 a  = Ag[(size_t)(m0 + m) * DIM4 + kq0 + kq];
            As[k][m] = a.x; As[k + 1][m] = a.y; As[k + 2][m] = a.z; As[k + 3][m] = a.w;
            float4 bv = Bg[(size_t)(n0 + m) * DIM4 + kq0 + kq];
            Bs[k][m] = bv.x; Bs[k + 1][m] = bv.y; Bs[k + 2][m] = bv.z; Bs[k + 3][m] = bv.w;
        }
        __syncthreads();

        #pragma unroll 16
        for (int k = 0; k < KC; k++) {
            float4 a  = *(const float4*)&As[k][ty * 4];
            float4 bv = *(const float4*)&Bs[k][tx * 4];
            acc[0][0] += a.x * bv.x; acc[0][1] += a.x * bv.y; acc[0][2] += a.x * bv.z; acc[0][3] += a.x * bv.w;
            acc[1][0] += a.y * bv.x; acc[1][1] += a.y * bv.y; acc[1][2] += a.y * bv.z; acc[1][3] += a.y * bv.w;
            acc[2][0] += a.z * bv.x; acc[2][1] += a.z * bv.y; acc[2][2] += a.z * bv.z; acc[2][3] += a.z * bv.w;
            acc[3][0] += a.w * bv.x; acc[3][1] += a.w * bv.y; acc[3][2] += a.w * bv.z; acc[3][3] += a.w * bv.w;
        }
    }

    int m = m0 + ty * 4;
    int n = n0 + tx * 4;
    float* outp = gSp + (size_t)kz * NV * NV;
    #pragma unroll
    for (int r = 0; r < 4; r++)
        *(float4*)&outp[(m + r) * NV + n] =
            make_float4(acc[r][0], acc[r][1], acc[r][2], acc[r][3]);
}

// ---------------------------------------------------------------------------
// Kernel 3: reduce the KSPLIT partial slabs into gS. float4 per thread.
// grid = 64 blocks x 256 threads covers 16384 float4 = 65536 floats.
// ---------------------------------------------------------------------------
__global__ __launch_bounds__(256) void reduce_kernel()
{
    int idx = blockIdx.x * 256 + threadIdx.x;   // float4 index
    const float4* p = (const float4*)gSp;
    float4 s = p[idx];
    #pragma unroll
    for (int k = 1; k < KSPLIT; k++) {
        float4 v = p[k * (NV * NV / 4) + idx];
        s.x += v.x; s.y += v.y; s.z += v.z; s.w += v.w;
    }
    ((float4*)gS)[idx] = s;
}

// ---------------------------------------------------------------------------
// Kernel 4: hinge loss + reduction. Single block, 1024 threads.
// ---------------------------------------------------------------------------
__global__ __launch_bounds__(1024) void loss_kernel(
    const int* __restrict__ ncl, const int* __restrict__ ncp,
    float* __restrict__ out)
{
    __shared__ float dg[256];   // diagonal of S
    __shared__ float rc[256];   // num_clips as float
    __shared__ float rp[256];   // num_caps as float

    int t = threadIdx.x;
    if (t < 256) {
        float nc = (float)ncl[t];
        float np = (float)ncp[t];
        rc[t] = nc; rp[t] = np;
        dg[t] = gS[t * 257] / (nc * np);
    }
    __syncthreads();

    float sum = 0.f;
    #pragma unroll
    for (int it = 0; it < 64; it++) {
        int idx = t + it * 1024;
        int i = idx >> 8;
        int j = idx & 255;
        float sv = gS[idx] / (rc[i] * rp[j]);
        if (i != j)
            sum += fmaxf(sv - dg[i], 0.f) + fmaxf(sv - dg[j], 0.f);
    }

    #pragma unroll
    for (int o = 16; o > 0; o >>= 1) sum += __shfl_down_sync(0xffffffffu, sum, o);
    __shared__ float ws[32];
    if ((t & 31) == 0) ws[t >> 5] = sum;
    __syncthreads();
    if (t < 32) {
        float v = ws[t];
        #pragma unroll
        for (int o = 16; o > 0; o >>= 1) v += __shfl_down_sync(0xffffffffu, v, o);
        if (t == 0) out[0] = v;
    }
}

extern "C" void kernel_launch(void* const* d_in, const int* in_sizes, int n_in,
                              void* d_out, int out_size)
{
    const float* im  = (const float*)d_in[0];
    const float* sc  = (const float*)d_in[1];
    const int*   ncl = (const int*)d_in[2];
    const int*   ncp = (const int*)d_in[3];

    seg_reduce_kernel<<<1024, 128>>>(im, sc, ncl, ncp);
    gemm_kernel<<<dim3(4, 4, KSPLIT), dim3(16, 16)>>>();
    reduce_kernel<<<64, 256>>>();
    loss_kernel<<<1, 1024>>>(ncl, ncp, (float*)d_out);
}